// round 3
// baseline (speedup 1.0000x reference)
#include <cuda_runtime.h>
#include <math.h>

#define NA 2304
#define N_PROP 2000
#define FC1_K 3136

#define OFF_RPN_LOGITS   0
#define OFF_RPN_DELTAS   4608
#define OFF_PROPOSALS    13824
#define OFF_ANCHORS      21824
#define OFF_RCNN_LOGITS  31040
#define OFF_RCNN_DELTAS  35040
#define OFF_RCNN_MASKS   43040
#define OFF_FINAL_DETS   435040
#define OFF_FINAL_MASKS  443040
#define OFF_FINAL_SCORES 835040
#define OFF_KEEP2        837040

// ---------------- scratch ----------------
__device__ __align__(16) float g_feat[64 * 256];
__device__ __align__(16) float g_h[64 * 256];
__device__ __align__(16) float g_scores[NA];
__device__ __align__(16) float g_boxes[NA * 4];
__device__ __align__(16) float g_sboxes[NA * 4];
__device__ int   g_order1[NA];
__device__ unsigned char g_keep1[NA];
__device__ __align__(16) float g_prop[N_PROP * 4];
__device__ unsigned char g_valid[N_PROP];
__device__ __align__(16) float g_pooled[N_PROP * FC1_K];
__device__ __align__(16) float g_h1[N_PROP * 512];
__device__ __align__(16) float g_h2[N_PROP * 512];
__device__ __align__(16) float g_dets[N_PROP * 4];
__device__ __align__(16) float g_sdets[N_PROP * 4];
__device__ float g_dscores[N_PROP];
__device__ float g_s2[N_PROP];
__device__ int   g_order2[N_PROP];
__device__ unsigned char g_keep2[N_PROP];

// ---------------- backbone ----------------
__global__ void k_backbone(const float* __restrict__ x, const float* __restrict__ w,
                           const float* __restrict__ b) {
    __shared__ float patch[768];
    int pos = blockIdx.x, py = pos >> 4, px = pos & 15;
    int t = threadIdx.x;  // 64
    for (int i = t; i < 768; i += 64) {
        int ci = i >> 8, rem = i & 255, ky = rem >> 4, kx = rem & 15;
        patch[i] = x[ci * 65536 + (py * 16 + ky) * 256 + (px * 16 + kx)];
    }
    __syncthreads();
    const float* wc = w + t * 768;
    float acc = b[t];
#pragma unroll 8
    for (int i = 0; i < 768; i++) acc += patch[i] * __ldg(&wc[i]);
    g_feat[t * 256 + pos] = fmaxf(acc, 0.f);
}

// ---------------- RPN 3x3 SAME conv ----------------
__global__ void k_rpnconv(const float* __restrict__ w, const float* __restrict__ b) {
    __shared__ float ws[576];
    int c = blockIdx.x, t = threadIdx.x;  // 256
    for (int i = t; i < 576; i += 256) ws[i] = w[c * 576 + i];
    __syncthreads();
    int y = t >> 4, x = t & 15;
    float acc = b[c];
    for (int ci = 0; ci < 64; ci++) {
        const float* f = g_feat + ci * 256;
#pragma unroll
        for (int ky = 0; ky < 3; ky++) {
            int yy = y + ky - 1;
            if (yy < 0 || yy > 15) continue;
#pragma unroll
            for (int kx = 0; kx < 3; kx++) {
                int xx = x + kx - 1;
                if (xx < 0 || xx > 15) continue;
                acc += __ldg(&f[yy * 16 + xx]) * ws[ci * 9 + ky * 3 + kx];
            }
        }
    }
    g_h[c * 256 + t] = fmaxf(acc, 0.f);
}

// ---------------- RPN heads + anchors + decode + clip ----------------
__global__ void k_rpnhead(const float* __restrict__ wcls, const float* __restrict__ bcls,
                          const float* __restrict__ wbox, const float* __restrict__ bbox,
                          float* __restrict__ out) {
    __shared__ float hv[64], lg[18], dl[36];
    int pos = blockIdx.x, y = pos >> 4, x = pos & 15;
    int t = threadIdx.x;  // 64
    hv[t] = g_h[t * 256 + pos];
    __syncthreads();
    if (t < 54) {
        int a = t / 6, j = t % 6;
        if (j < 2) {
            int o = a * 2 + j;
            float acc = bcls[o];
            const float* wr = wcls + o * 64;
            for (int ci = 0; ci < 64; ci++) acc += hv[ci] * wr[ci];
            lg[o] = acc;
            out[OFF_RPN_LOGITS + (pos * 9 + a) * 2 + j] = acc;
        } else {
            int o = a * 4 + (j - 2);
            float acc = bbox[o];
            const float* wr = wbox + o * 64;
            for (int ci = 0; ci < 64; ci++) acc += hv[ci] * wr[ci];
            dl[o] = acc;
            out[OFF_RPN_DELTAS + (pos * 9 + a) * 4 + (j - 2)] = acc;
        }
    }
    __syncthreads();
    if (t < 9) {
        int a = t;
        float l0 = lg[a * 2], l1 = lg[a * 2 + 1];
        float mx = fmaxf(l0, l1);
        float e0 = expf(l0 - mx), e1 = expf(l1 - mx);
        float sc = e1 / (e0 + e1);
        const float scl[3] = {32.f, 64.f, 128.f};
        const float rat[3] = {0.5f, 1.f, 2.f};
        float s = scl[a / 3], r = rat[a % 3];
        float ws = s * sqrtf(r), hs = s / sqrtf(r);
        float cx = ((float)x + 0.5f) * 16.f, cy = ((float)y + 0.5f) * 16.f;
        float a0 = cx - ws * 0.5f, a1 = cy - hs * 0.5f;
        float a2 = cx + ws * 0.5f, a3 = cy + hs * 0.5f;
        int ai = pos * 9 + a;
        out[OFF_ANCHORS + ai * 4 + 0] = a0;
        out[OFF_ANCHORS + ai * 4 + 1] = a1;
        out[OFF_ANCHORS + ai * 4 + 2] = a2;
        out[OFF_ANCHORS + ai * 4 + 3] = a3;
        float w = a2 - a0, h = a3 - a1;
        float ccx = a0 + 0.5f * w, ccy = a1 + 0.5f * h;
        float ncx = ccx + dl[a * 4 + 0] * w, ncy = ccy + dl[a * 4 + 1] * h;
        float nw = w * expf(dl[a * 4 + 2]), nh = h * expf(dl[a * 4 + 3]);
        g_scores[ai] = sc;
        g_boxes[ai * 4 + 0] = fminf(fmaxf(ncx - 0.5f * nw, 0.f), 255.f);
        g_boxes[ai * 4 + 1] = fminf(fmaxf(ncy - 0.5f * nh, 0.f), 255.f);
        g_boxes[ai * 4 + 2] = fminf(fmaxf(ncx + 0.5f * nw, 0.f), 255.f);
        g_boxes[ai * 4 + 3] = fminf(fmaxf(ncy + 0.5f * nh, 0.f), 255.f);
    }
}

// ---------------- stable descending sort ----------------
__device__ __forceinline__ unsigned int fmap(float s) {
    unsigned int u = __float_as_uint(s);
    return (u & 0x80000000u) ? ~u : (u | 0x80000000u);
}

template <int P>
__global__ void k_sort(int stage) {
    __shared__ unsigned long long keys[P];
    const float* scores = stage ? g_s2 : g_scores;
    const float* boxes = stage ? g_dets : g_boxes;
    int* order = stage ? g_order2 : g_order1;
    float* sboxes = stage ? g_sdets : g_sboxes;
    int n = stage ? N_PROP : NA;
    int t = threadIdx.x;  // 1024
    for (int i = t; i < P; i += 1024) {
        unsigned long long k = 0ull;
        if (i < n)
            k = ((unsigned long long)fmap(scores[i]) << 32) |
                (unsigned long long)(0xFFFFFFFFu - (unsigned)i);
        keys[i] = k;
    }
    __syncthreads();
    for (int k = 2; k <= P; k <<= 1) {
        for (int j = k >> 1; j > 0; j >>= 1) {
            for (int i = t; i < P; i += 1024) {
                int ixj = i ^ j;
                if (ixj > i) {
                    bool desc = ((i & k) == 0);
                    unsigned long long a = keys[i], b = keys[ixj];
                    if (desc ? (a < b) : (a > b)) { keys[i] = b; keys[ixj] = a; }
                }
            }
            __syncthreads();
        }
    }
    for (int r = t; r < n; r += 1024) {
        int o = (int)(0xFFFFFFFFu - (unsigned)keys[r]);
        order[r] = o;
        ((float4*)sboxes)[r] = ((const float4*)boxes)[o];
    }
}

// ---------------- sequential greedy NMS ----------------
__global__ void k_nms(int stage) {
    extern __shared__ float sm[];
    const float* sboxes = stage ? g_sdets : g_sboxes;
    unsigned char* keep = stage ? g_keep2 : g_keep1;
    int n = stage ? N_PROP : NA;
    float thr = stage ? 0.3f : 0.5f;
    float* bx = sm;
    float* ar = sm + n * 4;
    unsigned char* kp = (unsigned char*)(ar + n);
    int t = threadIdx.x;
    for (int i = t; i < n; i += blockDim.x) {
        float x1 = sboxes[i * 4], y1 = sboxes[i * 4 + 1];
        float x2 = sboxes[i * 4 + 2], y2 = sboxes[i * 4 + 3];
        bx[i * 4] = x1; bx[i * 4 + 1] = y1; bx[i * 4 + 2] = x2; bx[i * 4 + 3] = y2;
        ar[i] = fmaxf(x2 - x1, 0.f) * fmaxf(y2 - y1, 0.f);
        kp[i] = 1;
    }
    __syncthreads();
    for (int i = 0; i < n - 1; i++) {
        if (kp[i]) {
            float x1 = bx[i * 4], y1 = bx[i * 4 + 1], x2 = bx[i * 4 + 2], y2 = bx[i * 4 + 3];
            float ai = ar[i];
            for (int j = i + 1 + t; j < n; j += blockDim.x) {
                if (kp[j]) {
                    float inter = fmaxf(fminf(x2, bx[j * 4 + 2]) - fmaxf(x1, bx[j * 4]), 0.f) *
                                  fmaxf(fminf(y2, bx[j * 4 + 3]) - fmaxf(y1, bx[j * 4 + 1]), 0.f);
                    float iou = inter / (ai + ar[j] - inter + 1e-8f);
                    if (iou > thr) kp[j] = 0;
                }
            }
        }
        __syncthreads();
    }
    for (int i = t; i < n; i += blockDim.x) keep[i] = kp[i];
}

// ---------------- proposal compaction ----------------
__global__ void k_compact(float* __restrict__ out) {
    __shared__ int s[1024];
    int t = threadIdx.x;
    int b0 = t * 3;
    unsigned char ks[3] = {0, 0, 0};
    int c = 0;
#pragma unroll
    for (int q = 0; q < 3; q++) {
        int i = b0 + q;
        if (i < NA) { ks[q] = g_keep1[i]; c += ks[q]; }
    }
    s[t] = c;
    __syncthreads();
    for (int off = 1; off < 1024; off <<= 1) {
        int v = (t >= off) ? s[t - off] : 0;
        __syncthreads();
        s[t] += v;
        __syncthreads();
    }
    int K = s[1023];
    int rk = s[t] - c;
#pragma unroll
    for (int q = 0; q < 3; q++) {
        int i = b0 + q;
        if (i >= NA) break;
        int slot;
        if (ks[q]) { slot = rk; rk++; }
        else       { slot = K + (i - rk); }
        if (slot < N_PROP) {
            g_valid[slot] = ks[q];
            float v0 = 0.f, v1 = 0.f, v2 = 0.f, v3 = 0.f;
            if (ks[q]) {
                v0 = g_sboxes[i * 4];     v1 = g_sboxes[i * 4 + 1];
                v2 = g_sboxes[i * 4 + 2]; v3 = g_sboxes[i * 4 + 3];
            }
            g_prop[slot * 4 + 0] = v0; g_prop[slot * 4 + 1] = v1;
            g_prop[slot * 4 + 2] = v2; g_prop[slot * 4 + 3] = v3;
            out[OFF_PROPOSALS + slot * 4 + 0] = v0;
            out[OFF_PROPOSALS + slot * 4 + 1] = v1;
            out[OFF_PROPOSALS + slot * 4 + 2] = v2;
            out[OFF_PROPOSALS + slot * 4 + 3] = v3;
        }
    }
}

// ---------------- fused ROI: crop + pool + mask convs ----------------
#define ROI_SMEM_FLOATS (16384 + 36864 + 128)
#define ROI_SMEM_BYTES  (ROI_SMEM_FLOATS * 4)

__global__ void __launch_bounds__(256, 1)
k_roi(const float* __restrict__ wm1, const float* __restrict__ bm1,
      const float* __restrict__ wm2, const float* __restrict__ bm2,
      float* __restrict__ out) {
    extern __shared__ float smf[];
    float* crops = smf;               // 64 x 16 x 16 padded (data at [i+1][j+1])
    float* wsm   = smf + 16384;       // 64*64*9
    float* wy = smf + 16384 + 36864;  // 14
    float* wx = wy + 14;
    int* y0 = (int*)(wx + 14);
    int* y1 = y0 + 14;
    int* x0 = y1 + 14;
    int* x1 = x0 + 14;

    int n = blockIdx.x, t = threadIdx.x;

    for (int i = t; i < 16384; i += 256) crops[i] = 0.f;
    if (t < 28) {
        int i = t % 14;
        bool isY = t < 14;
        float c1 = g_prop[n * 4 + (isY ? 1 : 0)] * (1.f / 255.f);
        float c2 = g_prop[n * 4 + (isY ? 3 : 2)] * (1.f / 255.f);
        float f = (c1 + (c2 - c1) * ((float)i / 13.f)) * 15.f;
        float f0 = fminf(fmaxf(floorf(f), 0.f), 15.f);
        int i0 = (int)f0, i1 = min(i0 + 1, 15);
        float wgt = f - f0;
        if (isY) { y0[i] = i0; y1[i] = i1; wy[i] = wgt; }
        else     { x0[i] = i0; x1[i] = i1; wx[i] = wgt; }
    }
    __syncthreads();

    for (int idx = t; idx < 64 * 196; idx += 256) {
        int c = idx / 196, p = idx % 196, i = p / 14, j = p % 14;
        const float* f = g_feat + c * 256;
        float v00 = f[y0[i] * 16 + x0[j]], v01 = f[y0[i] * 16 + x1[j]];
        float v10 = f[y1[i] * 16 + x0[j]], v11 = f[y1[i] * 16 + x1[j]];
        float top = v00 * (1.f - wx[j]) + v01 * wx[j];
        float bot = v10 * (1.f - wx[j]) + v11 * wx[j];
        crops[c * 256 + (i + 1) * 16 + (j + 1)] = top * (1.f - wy[i]) + bot * wy[i];
    }
    for (int i4 = t; i4 < 9216; i4 += 256)
        ((float4*)wsm)[i4] = ((const float4*)wm1)[i4];
    __syncthreads();

    // 2x2 maxpool -> g_pooled
    for (int idx = t; idx < FC1_K; idx += 256) {
        int c = idx / 49, p = idx % 49, pi = p / 7, pj = p % 7;
        const float* base = crops + c * 256 + (2 * pi + 1) * 16 + (2 * pj + 1);
        g_pooled[n * FC1_K + idx] = fmaxf(fmaxf(base[0], base[1]), fmaxf(base[16], base[17]));
    }

    // mask conv1: thread = (co, quarter)
    int co = t >> 2, q = t & 3, qy = q >> 1, qx = q & 1;
    float acc[49];
#pragma unroll
    for (int i = 0; i < 49; i++) acc[i] = 0.f;
    const float* wrow = wsm + co * 576;
#pragma unroll 1
    for (int ci = 0; ci < 64; ci++) {
        const float* pc = crops + ci * 256 + qy * 7 * 16 + qx * 7;
        float w[9];
#pragma unroll
        for (int k = 0; k < 9; k++) w[k] = wrow[ci * 9 + k];
#pragma unroll
        for (int r = 0; r < 9; r++) {
            float row[9];
#pragma unroll
            for (int cc = 0; cc < 9; cc++) row[cc] = pc[r * 16 + cc];
#pragma unroll
            for (int dy = 0; dy < 3; dy++) {
                int i = r - dy;
                if (i >= 0 && i < 7) {
#pragma unroll
                    for (int j = 0; j < 7; j++) {
                        acc[i * 7 + j] += row[j + 0] * w[dy * 3 + 0];
                        acc[i * 7 + j] += row[j + 1] * w[dy * 3 + 1];
                        acc[i * 7 + j] += row[j + 2] * w[dy * 3 + 2];
                    }
                }
            }
        }
    }
    float b1 = bm1[co], w2c = wm2[co];
    __syncthreads();  // done reading crops

    // relu + 1x1 partials into reused crop smem: part[co*196 + q*49 + pp]
    float* part = crops;
#pragma unroll
    for (int pp = 0; pp < 49; pp++)
        part[co * 196 + q * 49 + pp] = fmaxf(acc[pp] + b1, 0.f) * w2c;
    __syncthreads();

    if (t < 196) {
        float s = bm2[0];
#pragma unroll 8
        for (int c = 0; c < 64; c++) s += part[c * 196 + t];
        int qq = t / 49, pp = t % 49;
        int gi = (qq >> 1) * 7 + pp / 7, gj = (qq & 1) * 7 + pp % 7;
        out[OFF_RCNN_MASKS + n * 196 + gi * 14 + gj] = s;
    }
}

// ---------------- tiled GEMM over internal buffers ----------------
// which=0: g_pooled[2000,3136] @ B -> g_h1 ; which=1: g_h1[2000,512] @ B -> g_h2
__global__ void k_gemm(int which, const float* __restrict__ B,
                       const float* __restrict__ bias) {
    const float* A = which ? g_h1 : g_pooled;
    float* C = which ? g_h2 : g_h1;
    const int K = which ? 512 : FC1_K;
    const int M = N_PROP, N = 512;

    __shared__ float As[16][65];
    __shared__ float Bs[16][64];
    int tid = threadIdx.x;
    int m0 = blockIdx.x * 64, n0 = blockIdx.y * 64;
    int ty = tid >> 4, tx = tid & 15;
    float acc[4][4];
#pragma unroll
    for (int i = 0; i < 4; i++)
#pragma unroll
        for (int j = 0; j < 4; j++) acc[i][j] = 0.f;

    int ra = tid >> 2, ca = (tid & 3) * 4;
    int rb = tid >> 4, cb = (tid & 15) * 4;

    for (int k0 = 0; k0 < K; k0 += 16) {
        float4 a4 = make_float4(0.f, 0.f, 0.f, 0.f);
        int m = m0 + ra;
        if (m < M) a4 = *(const float4*)&A[(size_t)m * K + k0 + ca];
        As[ca + 0][ra] = a4.x; As[ca + 1][ra] = a4.y;
        As[ca + 2][ra] = a4.z; As[ca + 3][ra] = a4.w;
        float4 b4 = *(const float4*)&B[(size_t)(k0 + rb) * N + n0 + cb];
        *(float4*)&Bs[rb][cb] = b4;
        __syncthreads();
#pragma unroll
        for (int kk = 0; kk < 16; kk++) {
            float a[4], b[4];
#pragma unroll
            for (int i = 0; i < 4; i++) a[i] = As[kk][ty * 4 + i];
#pragma unroll
            for (int j = 0; j < 4; j++) b[j] = Bs[kk][tx * 4 + j];
#pragma unroll
            for (int i = 0; i < 4; i++)
#pragma unroll
                for (int j = 0; j < 4; j++) acc[i][j] += a[i] * b[j];
        }
        __syncthreads();
    }
#pragma unroll
    for (int i = 0; i < 4; i++) {
        int m = m0 + ty * 4 + i;
        if (m < M) {
#pragma unroll
            for (int j = 0; j < 4; j++) {
                float v = fmaxf(acc[i][j] + bias[n0 + tx * 4 + j], 0.f);
                C[(size_t)m * N + n0 + tx * 4 + j] = v;
            }
        }
    }
}

// ---------------- RCNN heads + decode ----------------
__device__ __forceinline__ float wred(float v) {
#pragma unroll
    for (int o = 16; o; o >>= 1) v += __shfl_xor_sync(0xFFFFFFFFu, v, o);
    return v;
}

__global__ void k_rhead(const float* __restrict__ wrcls, const float* __restrict__ brcls,
                        const float* __restrict__ wrbox, const float* __restrict__ brbox,
                        float* __restrict__ out) {
    int w = threadIdx.x >> 5, lane = threadIdx.x & 31;
    int n = blockIdx.x * 8 + w;
    const float* h = g_h2 + n * 512;
    float p[6];
#pragma unroll
    for (int o = 0; o < 6; o++) p[o] = 0.f;
    for (int k = lane; k < 512; k += 32) {
        float hv = h[k];
        p[0] += hv * wrcls[k * 2 + 0];
        p[1] += hv * wrcls[k * 2 + 1];
        p[2] += hv * wrbox[k * 4 + 0];
        p[3] += hv * wrbox[k * 4 + 1];
        p[4] += hv * wrbox[k * 4 + 2];
        p[5] += hv * wrbox[k * 4 + 3];
    }
#pragma unroll
    for (int o = 0; o < 6; o++) p[o] = wred(p[o]);
    if (lane == 0) {
        float l0 = p[0] + brcls[0], l1 = p[1] + brcls[1];
        float d0 = p[2] + brbox[0], d1 = p[3] + brbox[1];
        float d2 = p[4] + brbox[2], d3 = p[5] + brbox[3];
        out[OFF_RCNN_LOGITS + n * 2 + 0] = l0;
        out[OFF_RCNN_LOGITS + n * 2 + 1] = l1;
        out[OFF_RCNN_DELTAS + n * 4 + 0] = d0;
        out[OFF_RCNN_DELTAS + n * 4 + 1] = d1;
        out[OFF_RCNN_DELTAS + n * 4 + 2] = d2;
        out[OFF_RCNN_DELTAS + n * 4 + 3] = d3;
        float mx = fmaxf(l0, l1);
        float e0 = expf(l0 - mx), e1 = expf(l1 - mx);
        float ds = e1 / (e0 + e1);
        g_dscores[n] = ds;
        float px1 = g_prop[n * 4], py1 = g_prop[n * 4 + 1];
        float px2 = g_prop[n * 4 + 2], py2 = g_prop[n * 4 + 3];
        float pw = px2 - px1, ph = py2 - py1;
        float cx = px1 + 0.5f * pw, cy = py1 + 0.5f * ph;
        float ncx = cx + d0 * pw, ncy = cy + d1 * ph;
        float nw = pw * expf(d2), nh = ph * expf(d3);
        g_dets[n * 4 + 0] = fminf(fmaxf(ncx - 0.5f * nw, 0.f), 255.f);
        g_dets[n * 4 + 1] = fminf(fmaxf(ncy - 0.5f * nh, 0.f), 255.f);
        g_dets[n * 4 + 2] = fminf(fmaxf(ncx + 0.5f * nw, 0.f), 255.f);
        g_dets[n * 4 + 3] = fminf(fmaxf(ncy + 0.5f * nh, 0.f), 255.f);
        g_s2[n] = g_valid[n] ? ds : -1.0f;
    }
}

// ---------------- finalize ----------------
__global__ void k_finalize(float* __restrict__ out) {
    int r = blockIdx.x, t = threadIdx.x;
    int o2 = g_order2[r];
    bool comb = g_keep2[r] && g_valid[o2];
    if (t == 0) {
        out[OFF_KEEP2 + r] = comb ? 1.f : 0.f;
        out[OFF_FINAL_SCORES + r] = comb ? g_dscores[o2] : 0.f;
        out[OFF_FINAL_DETS + r * 4 + 0] = comb ? g_sdets[r * 4 + 0] : 0.f;
        out[OFF_FINAL_DETS + r * 4 + 1] = comb ? g_sdets[r * 4 + 1] : 0.f;
        out[OFF_FINAL_DETS + r * 4 + 2] = comb ? g_sdets[r * 4 + 2] : 0.f;
        out[OFF_FINAL_DETS + r * 4 + 3] = comb ? g_sdets[r * 4 + 3] : 0.f;
    }
    if (t < 196) {
        float m = out[OFF_RCNN_MASKS + o2 * 196 + t];
        out[OFF_FINAL_MASKS + r * 196 + t] = comb ? (1.f / (1.f + expf(-m))) : 0.f;
    }
}

// ---------------- launch ----------------
extern "C" void kernel_launch(void* const* d_in, const int* in_sizes, int n_in,
                              void* d_out, int out_size) {
    const float* x      = (const float*)d_in[0];
    const float* w_bb   = (const float*)d_in[1];
    const float* b_bb   = (const float*)d_in[2];
    const float* w_rpn  = (const float*)d_in[3];
    const float* b_rpn  = (const float*)d_in[4];
    const float* w_cls  = (const float*)d_in[5];
    const float* b_cls  = (const float*)d_in[6];
    const float* w_box  = (const float*)d_in[7];
    const float* b_box  = (const float*)d_in[8];
    const float* w_fc1  = (const float*)d_in[9];
    const float* b_fc1  = (const float*)d_in[10];
    const float* w_fc2  = (const float*)d_in[11];
    const float* b_fc2  = (const float*)d_in[12];
    const float* w_rcls = (const float*)d_in[13];
    const float* b_rcls = (const float*)d_in[14];
    const float* w_rbox = (const float*)d_in[15];
    const float* b_rbox = (const float*)d_in[16];
    const float* w_m1   = (const float*)d_in[17];
    const float* b_m1   = (const float*)d_in[18];
    const float* w_m2   = (const float*)d_in[19];
    const float* b_m2   = (const float*)d_in[20];
    float* out = (float*)d_out;

    cudaFuncSetAttribute(k_roi, cudaFuncAttributeMaxDynamicSharedMemorySize, ROI_SMEM_BYTES);

    k_backbone<<<256, 64>>>(x, w_bb, b_bb);
    k_rpnconv<<<64, 256>>>(w_rpn, b_rpn);
    k_rpnhead<<<256, 64>>>(w_cls, b_cls, w_box, b_box, out);
    k_sort<4096><<<1, 1024>>>(0);
    k_nms<<<1, 1024, NA * 20 + NA>>>(0);
    k_compact<<<1, 1024>>>(out);
    k_roi<<<N_PROP, 256, ROI_SMEM_BYTES>>>(w_m1, b_m1, w_m2, b_m2, out);
    {
        dim3 g1(32, 8);
        k_gemm<<<g1, 256>>>(0, w_fc1, b_fc1);
        k_gemm<<<g1, 256>>>(1, w_fc2, b_fc2);
    }
    k_rhead<<<250, 256>>>(w_rcls, b_rcls, w_rbox, b_rbox, out);
    k_sort<2048><<<1, 1024>>>(1);
    k_nms<<<1, 1024, N_PROP * 20 + N_PROP>>>(1);
    k_finalize<<<N_PROP, 256>>>(out);
}